// round 2
// baseline (speedup 1.0000x reference)
#include <cuda_runtime.h>
#include <cuda_fp16.h>
#include <cstdint>

// Problem dims
#define MDIM 8192   // B*S
#define NDIM 4096
#define KDIM 4096

// GEMM tiling
#define TM 128
#define TN 128
#define KC 64                        // 64 fp16 = 128B per row (swizzle atom)
#define NSTAGE 3
#define NK (KDIM / KC)               // 64
#define A_TILE_BYTES (TM * KC * 2)   // 16384
#define B_TILE_BYTES (TN * KC * 2)   // 16384
#define STAGE_BYTES (A_TILE_BYTES + B_TILE_BYTES)   // 32768
#define SMEM_DYN (NSTAGE * STAGE_BYTES)             // 98304

// Scratch (allocation-free rule: __device__ globals)
__device__ uint4 g_A16[(MDIM * (size_t)KDIM) / 8];   // fp16 A, [M, K]
__device__ uint4 g_W16[(NDIM * (size_t)KDIM) / 8];   // fp16 W^T, [N, K]

// ---------------------------------------------------------------------------
// helpers
// ---------------------------------------------------------------------------
__device__ __forceinline__ uint32_t smem_u32(const void* p) {
    uint32_t r;
    asm("{ .reg .u64 t; cvta.to.shared.u64 t, %1; cvt.u32.u64 %0, t; }"
        : "=r"(r) : "l"(p));
    return r;
}

__device__ __forceinline__ void cp_async16(uint32_t s, const void* g) {
    asm volatile("cp.async.cg.shared.global [%0], [%1], 16;"
                 :: "r"(s), "l"(__cvta_generic_to_global(g)) : "memory");
}

#define LDM_X4(r, addr)                                                        \
    asm volatile("ldmatrix.sync.aligned.m8n8.x4.shared.b16 {%0,%1,%2,%3}, [%4];" \
                 : "=r"((r)[0]), "=r"((r)[1]), "=r"((r)[2]), "=r"((r)[3])      \
                 : "r"(addr))

__device__ __forceinline__ void mma16816(float* d, const uint32_t* a,
                                         const uint32_t* b) {
    asm volatile(
        "mma.sync.aligned.m16n8k16.row.col.f32.f16.f16.f32 "
        "{%0,%1,%2,%3}, {%4,%5,%6,%7}, {%8,%9}, {%0,%1,%2,%3};"
        : "+f"(d[0]), "+f"(d[1]), "+f"(d[2]), "+f"(d[3])
        : "r"(a[0]), "r"(a[1]), "r"(a[2]), "r"(a[3]), "r"(b[0]), "r"(b[1]));
}

// ---------------------------------------------------------------------------
// Pre-pass 1: A fp32 -> fp16
// ---------------------------------------------------------------------------
__global__ void __launch_bounds__(256) k_aconv(const float* __restrict__ in) {
    size_t i = ((size_t)blockIdx.x * 256 + threadIdx.x) * 8;
    float4 a = *(const float4*)(in + i);
    float4 b = *(const float4*)(in + i + 4);
    union { __half2 h[4]; uint4 u; } pk;
    pk.h[0] = __floats2half2_rn(a.x, a.y);
    pk.h[1] = __floats2half2_rn(a.z, a.w);
    pk.h[2] = __floats2half2_rn(b.x, b.y);
    pk.h[3] = __floats2half2_rn(b.z, b.w);
    g_A16[i >> 3] = pk.u;
}

// ---------------------------------------------------------------------------
// Pre-pass 2: GPTQ int4 dequant -> fp16, transposed to [N, K]
// w[k,n] = ((q[k/8,n] >> 4*(k%8)) & 15 - z[g,n]) * s[g,n],  g = k/128
// ---------------------------------------------------------------------------
__global__ void __launch_bounds__(256) k_dequant(const int* __restrict__ qw,
                                                 const float* __restrict__ sc,
                                                 const int* __restrict__ qz) {
    int idx = blockIdx.x * 256 + threadIdx.x;   // over (K/8)*N, n fastest
    int n  = idx & (NDIM - 1);
    int kk = idx >> 12;                         // k/8
    int g  = kk >> 4;                           // group = (kk*8)/128
    int q  = qw[idx];
    int zw = qz[(g << 9) | (n >> 3)];
    float z = (float)((zw >> ((n & 7) << 2)) & 15);
    float s = sc[(g << 12) | n];
    union { __half2 h[4]; uint4 u; } pk;
#pragma unroll
    for (int j = 0; j < 4; ++j) {
        float w0 = ((float)((q >> (8 * j))     & 15) - z) * s;
        float w1 = ((float)((q >> (8 * j + 4)) & 15) - z) * s;
        pk.h[j] = __floats2half2_rn(w0, w1);
    }
    __half* W = (__half*)g_W16;
    *(uint4*)(W + (size_t)n * KDIM + kk * 8) = pk.u;
}

// ---------------------------------------------------------------------------
// Main GEMM: C = A @ W^T + bias + residual
// 128x128 CTA tile, 8 warps (4m x 2n), warp tile 32x64, mma.sync m16n8k16,
// 3-stage cp.async pipeline, swizzled 128B smem rows.
// ---------------------------------------------------------------------------
__global__ void __launch_bounds__(256, 2)
k_gemm(const float* __restrict__ residual, const float* __restrict__ bias,
       float* __restrict__ out) {
    extern __shared__ char smem_raw[];
    const uint32_t sbase = smem_u32(smem_raw);

    const int tid  = threadIdx.x;
    const int wid  = tid >> 5;
    const int lane = tid & 31;
    const int warp_m = wid & 3;   // 4 warps along M (32 rows each)
    const int warp_n = wid >> 2;  // 2 warps along N (64 cols each)

    // L2-friendly raster: supertiles of 8 m-tiles x 32 n-tiles
    const int bid = blockIdx.x;
    const int tm_ = ((bid >> 8) << 3) | (bid & 7);
    const int tn_ = (bid >> 3) & 31;

    const __half* A16 = (const __half*)g_A16;
    const __half* W16 = (const __half*)g_W16;
    const __half* gA = A16 + (size_t)tm_ * TM * KDIM;
    const __half* gB = W16 + (size_t)tn_ * TN * KDIM;

    // ldmatrix per-lane metadata
    const int tileid = lane >> 3, r8 = lane & 7;
    // A: x4 over m16k16 -> tiles (m_lo,k_lo),(m_hi,k_lo),(m_lo,k_hi),(m_hi,k_hi)
    uint32_t aoff[2]; int asw[2];
    const int achk = tileid >> 1;
#pragma unroll
    for (int mt = 0; mt < 2; ++mt) {
        int ar = warp_m * 32 + mt * 16 + ((tileid & 1) << 3) + r8;
        aoff[mt] = (uint32_t)(ar << 7);
        asw[mt] = ar & 7;
    }
    // B: x4 over n16k16 -> groups (n_lo,k_lo),(n_lo,k_hi),(n_hi,k_lo),(n_hi,k_hi)
    uint32_t boff[4]; int bsw[4];
    const int bchk = tileid & 1;
#pragma unroll
    for (int nt = 0; nt < 4; ++nt) {
        int br = warp_n * 64 + nt * 16 + ((tileid >> 1) << 3) + r8;
        boff[nt] = (uint32_t)(br << 7);
        bsw[nt] = br & 7;
    }

    // Stage loader: 2048 x 16B (A+B) across 256 threads, XOR-swizzled rows
    auto load_stage = [&](int c, int slot) {
        const uint32_t sA = sbase + slot * STAGE_BYTES;
        const __half* pA = gA + c * KC;
        const __half* pB = gB + c * KC;
#pragma unroll
        for (int rep = 0; rep < 4; ++rep) {
            int idx = tid + rep * 256;
            int row = idx >> 3;
            int c16 = idx & 7;
            uint32_t soff = (uint32_t)(row << 7) |
                            (uint32_t)((c16 ^ (row & 7)) << 4);
            cp_async16(sA + soff, pA + (size_t)row * KDIM + c16 * 8);
            cp_async16(sA + A_TILE_BYTES + soff, pB + (size_t)row * KDIM + c16 * 8);
        }
    };

    float acc[2][8][4];
#pragma unroll
    for (int mt = 0; mt < 2; ++mt)
#pragma unroll
        for (int nt = 0; nt < 8; ++nt)
#pragma unroll
            for (int j = 0; j < 4; ++j) acc[mt][nt][j] = 0.f;

    // Prologue
#pragma unroll
    for (int c = 0; c < NSTAGE - 1; ++c) {
        load_stage(c, c);
        asm volatile("cp.async.commit_group;" ::: "memory");
    }

#pragma unroll 1
    for (int i = 0; i < NK; ++i) {
        const int slot = i % NSTAGE;
        asm volatile("cp.async.wait_group 1;" ::: "memory");
        __syncthreads();

        const int c = i + NSTAGE - 1;
        if (c < NK) load_stage(c, c % NSTAGE);
        asm volatile("cp.async.commit_group;" ::: "memory");

        const uint32_t sA = sbase + slot * STAGE_BYTES;
        const uint32_t sB = sA + A_TILE_BYTES;

#pragma unroll
        for (int s = 0; s < 4; ++s) {   // 4 x k16 within KC=64
            uint32_t a[2][4], b[4][4];
#pragma unroll
            for (int mt = 0; mt < 2; ++mt)
                LDM_X4(a[mt], sA + aoff[mt] +
                              (uint32_t)((((s << 1) + achk) ^ asw[mt]) << 4));
#pragma unroll
            for (int nt = 0; nt < 4; ++nt)
                LDM_X4(b[nt], sB + boff[nt] +
                              (uint32_t)((((s << 1) + bchk) ^ bsw[nt]) << 4));
#pragma unroll
            for (int mt = 0; mt < 2; ++mt)
#pragma unroll
                for (int nt = 0; nt < 4; ++nt) {
                    mma16816(acc[mt][2 * nt],     a[mt], b[nt]);
                    mma16816(acc[mt][2 * nt + 1], a[mt], b[nt] + 2);
                }
        }
    }

    // Epilogue: fp32 acc + bias + residual -> out
    const int r  = lane >> 2;
    const int c2 = (lane & 3) * 2;
    const int mbase = tm_ * TM + warp_m * 32;
    const int nbase = tn_ * TN + warp_n * 64;
#pragma unroll
    for (int mt = 0; mt < 2; ++mt) {
#pragma unroll
        for (int half = 0; half < 2; ++half) {   // rows r and r+8
            const size_t m = (size_t)(mbase + mt * 16 + r + half * 8);
            const float* rp = residual + m * NDIM + nbase;
            float* op = out + m * NDIM + nbase;
#pragma unroll
            for (int nt = 0; nt < 8; ++nt) {
                const int n = nt * 8 + c2;
                float2 res = *(const float2*)(rp + n);
                float2 bz  = *(const float2*)(bias + nbase + n);
                float2 o;
                o.x = acc[mt][nt][2 * half]     + bz.x + res.x;
                o.y = acc[mt][nt][2 * half + 1] + bz.y + res.y;
                *(float2*)(op + n) = o;
            }
        }
    }
}

// ---------------------------------------------------------------------------
extern "C" void kernel_launch(void* const* d_in, const int* in_sizes, int n_in,
                              void* d_out, int out_size) {
    const float* input    = (const float*)d_in[0];   // [2,4096,4096] f32
    const float* residual = (const float*)d_in[1];   // [2,4096,4096] f32
    const int*   qweight  = (const int*)d_in[2];     // [512,4096] i32
    const float* scales   = (const float*)d_in[3];   // [32,4096] f32
    const int*   qzeros   = (const int*)d_in[4];     // [32,512] i32
    const float* bias     = (const float*)d_in[5];   // [4096] f32
    float* out = (float*)d_out;

    cudaFuncSetAttribute(k_gemm, cudaFuncAttributeMaxDynamicSharedMemorySize,
                         SMEM_DYN);

    k_aconv<<<(MDIM * (size_t)KDIM) / 8 / 256, 256>>>(input);
    k_dequant<<<(KDIM / 8) * NDIM / 256, 256>>>(qweight, scales, qzeros);

    const int nblocks = (MDIM / TM) * (NDIM / TN);   // 2048
    k_gemm<<<nblocks, 256, SMEM_DYN>>>(residual, bias, out);
}